// round 7
// baseline (speedup 1.0000x reference)
#include <cuda_runtime.h>
#include <math.h>

#define BB 8
#define TT 1024
#define DD 1024
#define HH 16
#define D3 3072

// ---------------- scratch (static device arrays; no runtime allocation) ----------------
__device__ float g_qkv[25165824];   // [B,T,3D]
__device__ float g_GI [25165824];   // [B,T,3D]  x@w_ih^T + b_ih
__device__ float g_S  [134217728];  // [B,H,T,T] attention scores
__device__ float g_ctx[8388608];    // [B,T,D]
__device__ float g_A  [8388608];    // [B,T,D]   attention output
__device__ float g_AG [8388608];    // [B,T,D]   a-part of gate preact (incl. gate_b)
__device__ float g_Ht [8192];       // transposed hidden state [d][b] (single buffer)
__device__ float g_H1t[8192];       // transposed post-GRU state [d][b]
__device__ unsigned g_tagH [1024];  // per-dim version tags for h
__device__ unsigned g_tagH1[1024];  // per-dim version tags for h1
// probe-private state (self-contained; never touches real state)
__device__ float g_HtP [8192];
__device__ float g_H1tP[8192];
__device__ unsigned g_tagHP [1024];
__device__ unsigned g_tagH1P[1024];
__device__ float g_probeOut[8192];

// ---------------- packed f32x2 helpers ----------------
__device__ __forceinline__ void fma2(unsigned long long& d, unsigned long long a,
                                     unsigned long long b, unsigned long long c)
{
    asm("fma.rn.f32x2 %0, %1, %2, %3;" : "=l"(d) : "l"(a), "l"(b), "l"(c));
}
__device__ __forceinline__ unsigned long long add2(unsigned long long a, unsigned long long b)
{
    unsigned long long d;
    asm("add.rn.f32x2 %0, %1, %2;" : "=l"(d) : "l"(a), "l"(b));
    return d;
}
__device__ __forceinline__ unsigned long long pack2(float x)
{
    unsigned long long d; unsigned u = __float_as_uint(x);
    asm("mov.b64 %0, {%1, %2};" : "=l"(d) : "r"(u), "r"(u));
    return d;
}
__device__ __forceinline__ void unpack2(unsigned long long v, float& lo, float& hi)
{
    unsigned a, b;
    asm("mov.b64 {%0, %1}, %2;" : "=r"(a), "=r"(b) : "l"(v));
    lo = __uint_as_float(a); hi = __uint_as_float(b);
}
__device__ __forceinline__ float fsig(float x)
{
    return __fdividef(1.f, 1.f + __expf(-x));
}
__device__ __forceinline__ float ftanh(float x)
{
    return 1.f - __fdividef(2.f, __expf(2.f * x) + 1.f);
}

// ---------------- 128x128 tiled SGEMM (f32x2 core): C = scale*(A@op(B)) + bias ----------------
#define GEMM_LOAD(buf, kofs) do {                                               \
    float4 va = *(const float4*)&A[(long long)ar*lda + (kofs) + aq];            \
    As[buf][aq+0][ar]=va.x; As[buf][aq+1][ar]=va.y;                             \
    As[buf][aq+2][ar]=va.z; As[buf][aq+3][ar]=va.w;                             \
    if constexpr (TB) {                                                         \
      if (TN == 128 || t < 128) {                                               \
        float4 vb = *(const float4*)&Bp[(n0 + ar)*ldb + (kofs) + aq];           \
        Bs[buf][aq+0][ar]=vb.x; Bs[buf][aq+1][ar]=vb.y;                         \
        Bs[buf][aq+2][ar]=vb.z; Bs[buf][aq+3][ar]=vb.w;                         \
      }                                                                         \
    } else {                                                                    \
      if constexpr (TN == 128) {                                                \
        int kk = t >> 5, nn = (t & 31) * 4;                                     \
        *(float4*)&Bs[buf][kk][nn] =                                            \
            *(const float4*)&Bp[(long long)((kofs)+kk)*ldb + n0 + nn];          \
      } else {                                                                  \
        if (t < 128) { int kk = t >> 4, nn = (t & 15) * 4;                      \
          *(float4*)&Bs[buf][kk][nn] =                                          \
              *(const float4*)&Bp[(long long)((kofs)+kk)*ldb + n0 + nn]; }      \
      }                                                                         \
    }                                                                           \
  } while (0)

template<int TN, bool TB>
__global__ __launch_bounds__(256) void gemm_k(
    const float* __restrict__ A0, int lda, long long sA1, long long sA2,
    const float* __restrict__ B0, int ldb, long long sB1, long long sB2,
    float* __restrict__ C0, int ldc, long long sC1, long long sC2,
    int K, int Z2, const float* __restrict__ bias, float scale)
{
    constexpr int NJ = TN / 16;     // 8 or 4
    constexpr int NP = NJ / 2;      // accumulator pairs: 4 or 2
    int z  = blockIdx.z;
    int z1 = z / Z2, z2 = z - z1 * Z2;
    const float* A  = A0 + z1 * sA1 + z2 * sA2 + (long long)blockIdx.y * 128 * lda;
    const float* Bp = B0 + z1 * sB1 + z2 * sB2;
    float*       C  = C0 + z1 * sC1 + z2 * sC2 + (long long)blockIdx.y * 128 * ldc
                         + (long long)blockIdx.x * TN;
    long long n0 = (long long)blockIdx.x * TN;

    __shared__ float As[2][8][128];
    __shared__ float Bs[2][8][TN];
    int t = threadIdx.x, tx = t & 15, ty = t >> 4;
    int ar = t >> 1, aq = (t & 1) * 4;

    unsigned long long acc2[8][NP];
    #pragma unroll
    for (int i = 0; i < 8; i++)
        #pragma unroll
        for (int j = 0; j < NP; j++) acc2[i][j] = 0ull;

    int nk = K >> 3;
    GEMM_LOAD(0, 0);
    __syncthreads();

    for (int kt = 0; kt < nk; kt++) {
        int cb = kt & 1, nb = cb ^ 1;
        if (kt + 1 < nk) { GEMM_LOAD(nb, (kt + 1) << 3); }
        #pragma unroll
        for (int kk = 0; kk < 8; kk++) {
            float4 a0 = *(const float4*)&As[cb][kk][ty * 4];
            float4 a1 = *(const float4*)&As[cb][kk][ty * 4 + 64];
            ulonglong2 b01 = *(const ulonglong2*)&Bs[cb][kk][tx * 4];
            float av[8] = {a0.x,a0.y,a0.z,a0.w,a1.x,a1.y,a1.z,a1.w};
            if constexpr (NP == 4) {
                ulonglong2 b23 = *(const ulonglong2*)&Bs[cb][kk][tx * 4 + 64];
                #pragma unroll
                for (int i = 0; i < 8; i++) {
                    unsigned long long pa = pack2(av[i]);
                    fma2(acc2[i][0], b01.x, pa, acc2[i][0]);
                    fma2(acc2[i][1], b01.y, pa, acc2[i][1]);
                    fma2(acc2[i][2], b23.x, pa, acc2[i][2]);
                    fma2(acc2[i][3], b23.y, pa, acc2[i][3]);
                }
            } else {
                #pragma unroll
                for (int i = 0; i < 8; i++) {
                    unsigned long long pa = pack2(av[i]);
                    fma2(acc2[i][0], b01.x, pa, acc2[i][0]);
                    fma2(acc2[i][1], b01.y, pa, acc2[i][1]);
                }
            }
        }
        __syncthreads();
    }

    #pragma unroll
    for (int i = 0; i < 8; i++) {
        int row = (i < 4) ? (ty * 4 + i) : (64 + ty * 4 + (i - 4));
        #pragma unroll
        for (int jh = 0; jh < NP / 2; jh++) {
            int col = tx * 4 + jh * 64;
            float4 v;
            unpack2(acc2[i][jh*2+0], v.x, v.y);
            unpack2(acc2[i][jh*2+1], v.z, v.w);
            v.x *= scale; v.y *= scale; v.z *= scale; v.w *= scale;
            if (bias) {
                v.x += bias[n0+col]; v.y += bias[n0+col+1];
                v.z += bias[n0+col+2]; v.w += bias[n0+col+3];
            }
            *(float4*)&C[(long long)row * ldc + col] = v;
        }
    }
}

// ---------------- row softmax over 1024 columns ----------------
__global__ __launch_bounds__(256) void softmax_k(float* __restrict__ S)
{
    long long row = blockIdx.x;
    float* p = S + row * (long long)TT;
    int t = threadIdx.x;
    float v0 = p[t], v1 = p[t + 256], v2 = p[t + 512], v3 = p[t + 768];
    float m = fmaxf(fmaxf(v0, v1), fmaxf(v2, v3));
    __shared__ float sredm[8];
    __shared__ float sreds[8];
    #pragma unroll
    for (int o = 16; o; o >>= 1) m = fmaxf(m, __shfl_xor_sync(0xffffffffu, m, o));
    if ((t & 31) == 0) sredm[t >> 5] = m;
    __syncthreads();
    m = fmaxf(fmaxf(fmaxf(sredm[0], sredm[1]), fmaxf(sredm[2], sredm[3])),
              fmaxf(fmaxf(sredm[4], sredm[5]), fmaxf(sredm[6], sredm[7])));
    v0 = expf(v0 - m); v1 = expf(v1 - m); v2 = expf(v2 - m); v3 = expf(v3 - m);
    float s = (v0 + v1) + (v2 + v3);
    #pragma unroll
    for (int o = 16; o; o >>= 1) s += __shfl_xor_sync(0xffffffffu, s, o);
    if ((t & 31) == 0) sreds[t >> 5] = s;
    __syncthreads();
    s = ((sreds[0] + sreds[1]) + (sreds[2] + sreds[3]))
      + ((sreds[4] + sreds[5]) + (sreds[6] + sreds[7]));
    float inv = 1.f / s;
    p[t] = v0 * inv; p[t + 256] = v1 * inv; p[t + 512] = v2 * inv; p[t + 768] = v3 * inv;
}

// ---------------- state / tag reset (real recurrence only) ----------------
__global__ void reset_k()
{
    int i = blockIdx.x * blockDim.x + threadIdx.x;
    if (i < BB * DD) { g_Ht[i] = 0.f; g_H1t[i] = 0.f; }
    if (i < DD) { g_tagH[i] = 0u; g_tagH1[i] = 0u; }
}

// ---------------- persistent recurrent kernel (per-dim tagged dataflow) ----------------
#define GBLK 128
#define PTH  512

// Warp-coalesced wait: all 64 tags for this warp's k-range reach tgt.
__device__ __forceinline__ void wait_tags(const unsigned* tags, int w, unsigned tgt)
{
    int lane = threadIdx.x & 31;
    const unsigned* p0 = tags + w * 64 + lane;
    const unsigned* p1 = p0 + 32;
    unsigned v0, v1;
    do {
        asm volatile("ld.acquire.gpu.u32 %0, [%1];" : "=r"(v0) : "l"(p0) : "memory");
        asm volatile("ld.acquire.gpu.u32 %0, [%1];" : "=r"(v1) : "l"(p1) : "memory");
    } while (!__all_sync(0xffffffffu, (v0 >= tgt) & (v1 >= tgt)));
}

// NTOK tokens; PROBE uses self-epoch-basing (no reset launch needed) and dummy output.
template<int NTOK, bool PROBE>
__global__ __launch_bounds__(PTH, 1) void recur_t(
    const float* __restrict__ w_hh, const float* __restrict__ b_hh,
    const float* __restrict__ gate_w,
    const float* __restrict__ GI, const float* __restrict__ Av,
    const float* __restrict__ AGv,
    float* __restrict__ Ht, float* __restrict__ H1t,
    unsigned* __restrict__ tagH, unsigned* __restrict__ tagH1,
    float* __restrict__ out)
{
    __shared__ unsigned long long part[16 * 96];   // per-warp partials
    __shared__ unsigned long long ghs[96];         // phase1 reduced (u64 pairs)
    __shared__ unsigned long long g2s[32];         // phase2 reduced
    __shared__ float bs1[24];

    int t = threadIdx.x, g = blockIdx.x;
    int d0 = g * 8;
    int w = t >> 5, lane = t & 31;

    int rsub = lane >> 2, kq1 = lane & 3;   // phase1 roles
    int rg2 = lane >> 3, kq2 = lane & 7;    // phase2 roles
    int ed = t >> 3, eb = t & 7;            // elementwise roles (t<64)
    int dg = d0 + ed;
    unsigned pubmask = 0xFFu << ((ed & 3) * 8);

    // tags are only ever written by their owner block -> own-tag read is a safe epoch base
    unsigned base = 0;
    if (PROBE) base = __ldcg(&tagH[d0]);

    // ---- weights resident in registers ----
    float w1[3][16];
    #pragma unroll
    for (int q = 0; q < 3; q++) {
        int rho = rsub * 3 + q;
        const float* wr = w_hh + (size_t)((rho >> 3) * DD + d0 + (rho & 7)) * DD
                        + w * 64 + kq1;
        #pragma unroll
        for (int i = 0; i < 16; i++) w1[q][i] = wr[4 * i];
    }
    float w2[2][8];
    #pragma unroll
    for (int r = 0; r < 2; r++) {
        const float* wr = gate_w + (size_t)(d0 + rg2 * 2 + r) * (2 * DD)
                        + w * 64 + kq2;
        #pragma unroll
        for (int i = 0; i < 8; i++) w2[r][i] = wr[8 * i];
    }
    if (t < 24) bs1[t] = b_hh[(t >> 3) * DD + d0 + (t & 7)];
    __syncthreads();

    unsigned e = 0;
    float h_own = 0.f, h1_own = 0.f;

    const ulonglong2* Hg  = (const ulonglong2*)Ht;
    const ulonglong2* H1g = (const ulonglong2*)H1t;

    for (int tok = 0; tok < NTOK; tok++) {
        float gir = 0, giz = 0, gin = 0, av = 0, agv = 0;
        if (t < 64) {
            size_t gb = ((size_t)(eb * TT + tok)) * D3 + dg;
            gir = __ldg(&GI[gb]); giz = __ldg(&GI[gb + DD]); gin = __ldg(&GI[gb + 2 * DD]);
            size_t ab = ((size_t)(eb * TT + tok)) * DD + dg;
            av = __ldg(&Av[ab]); agv = __ldg(&AGv[ab]);
        }
        #pragma unroll 1
        for (int s = 0; s < 4; s++) {
            // ---- phase 1: gh = W_hh . h ----
            {
                wait_tags(tagH, w, base + e);
                unsigned long long acc[12];
                #pragma unroll
                for (int j = 0; j < 12; j++) acc[j] = 0ull;
                int kb = w * 64 + kq1;
                #pragma unroll
                for (int i = 0; i < 16; i++) {
                    int k = kb + 4 * i;
                    ulonglong2 p0 = __ldcg(&Hg[k * 2]);
                    ulonglong2 p1 = __ldcg(&Hg[k * 2 + 1]);
                    #pragma unroll
                    for (int q = 0; q < 3; q++) {
                        unsigned long long wd = pack2(w1[q][i]);
                        fma2(acc[q*4+0], p0.x, wd, acc[q*4+0]);
                        fma2(acc[q*4+1], p0.y, wd, acc[q*4+1]);
                        fma2(acc[q*4+2], p1.x, wd, acc[q*4+2]);
                        fma2(acc[q*4+3], p1.y, wd, acc[q*4+3]);
                    }
                }
                #pragma unroll
                for (int o = 1; o <= 2; o <<= 1)
                    #pragma unroll
                    for (int j = 0; j < 12; j++)
                        acc[j] = add2(acc[j], __shfl_xor_sync(0xffffffffu, acc[j], o));
                if (kq1 == 0) {
                    #pragma unroll
                    for (int j = 0; j < 12; j++) part[w * 96 + rsub * 12 + j] = acc[j];
                }
            }
            __syncthreads();
            if (t < 96) {
                unsigned long long d = part[t];
                #pragma unroll
                for (int wv = 1; wv < 16; wv++) d = add2(d, part[wv * 96 + t]);
                ghs[t] = d;
            }
            __syncthreads();

            // ---- GRU elementwise -> publish h1 ----
            if (t < 64) {
                const float* ghf = (const float*)ghs;
                float gh[3];
                #pragma unroll
                for (int c = 0; c < 3; c++) {
                    int rho = c * 8 + ed;
                    int o = (rho / 3) * 12 + (rho % 3) * 4 + (eb >> 1);
                    gh[c] = ghf[o * 2 + (eb & 1)] + bs1[rho];
                }
                float rr = fsig(gir + gh[0]);
                float zz = fsig(giz + gh[1]);
                float nn = ftanh(gin + rr * gh[2]);
                h1_own = (1.f - zz) * nn + zz * h_own;
                __stcg(&H1t[dg * 8 + eb], h1_own);
                __syncwarp(pubmask);
                if (eb == 0) {
                    unsigned tg = base + e + 1;
                    asm volatile("st.release.gpu.u32 [%0], %1;"
                                 :: "l"(&tagH1[dg]), "r"(tg) : "memory");
                }
            }

            // ---- phase 2: gate dot ----
            {
                wait_tags(tagH1, w, base + e + 1);
                unsigned long long a2[8];
                #pragma unroll
                for (int j = 0; j < 8; j++) a2[j] = 0ull;
                int kb = w * 64 + kq2;
                #pragma unroll
                for (int i = 0; i < 8; i++) {
                    int k = kb + 8 * i;
                    ulonglong2 p0 = __ldcg(&H1g[k * 2]);
                    ulonglong2 p1 = __ldcg(&H1g[k * 2 + 1]);
                    #pragma unroll
                    for (int r = 0; r < 2; r++) {
                        unsigned long long wd = pack2(w2[r][i]);
                        fma2(a2[r*4+0], p0.x, wd, a2[r*4+0]);
                        fma2(a2[r*4+1], p0.y, wd, a2[r*4+1]);
                        fma2(a2[r*4+2], p1.x, wd, a2[r*4+2]);
                        fma2(a2[r*4+3], p1.y, wd, a2[r*4+3]);
                    }
                }
                #pragma unroll
                for (int o = 1; o <= 4; o <<= 1)
                    #pragma unroll
                    for (int j = 0; j < 8; j++)
                        a2[j] = add2(a2[j], __shfl_xor_sync(0xffffffffu, a2[j], o));
                if (kq2 == 0) {
                    #pragma unroll
                    for (int j = 0; j < 8; j++) part[w * 32 + rg2 * 8 + j] = a2[j];
                }
            }
            __syncthreads();
            if (t < 32) {
                unsigned long long d = part[t];
                #pragma unroll
                for (int wv = 1; wv < 16; wv++) d = add2(d, part[wv * 32 + t]);
                g2s[t] = d;
            }
            __syncthreads();

            // ---- gate elementwise -> publish new h (+ output on last sub-step) ----
            if (t < 64) {
                const float* g2f = (const float*)g2s;
                float dot = g2f[ed * 8 + eb];
                float gv  = fsig(dot + agv);
                h_own = gv * h1_own + (1.f - gv) * av;
                __stcg(&Ht[dg * 8 + eb], h_own);
                if (PROBE) {
                    if (s == 3) out[dg * 8 + eb] = h_own;
                } else {
                    if (s == 3) out[((size_t)(eb * TT + tok)) * DD + dg] = h_own;
                }
                __syncwarp(pubmask);
                if (eb == 0) {
                    unsigned tg = base + e + 1;
                    asm volatile("st.release.gpu.u32 [%0], %1;"
                                 :: "l"(&tagH[dg]), "r"(tg) : "memory");
                }
            }
            e++;
        }
    }
}

// ---------------- launch ----------------
extern "C" void kernel_launch(void* const* d_in, const int* in_sizes, int n_in,
                              void* d_out, int out_size)
{
    (void)in_sizes; (void)n_in; (void)out_size;
    const float* x   = (const float*)d_in[0];
    const float* ipw = (const float*)d_in[1];
    const float* ipb = (const float*)d_in[2];
    const float* opw = (const float*)d_in[3];
    const float* opb = (const float*)d_in[4];
    const float* wih = (const float*)d_in[5];
    const float* whh = (const float*)d_in[6];
    const float* bih = (const float*)d_in[7];
    const float* bhh = (const float*)d_in[8];
    const float* gw  = (const float*)d_in[9];
    const float* gb  = (const float*)d_in[10];
    float* out = (float*)d_out;

    float *qkv, *GI, *S, *ctx, *A, *AG;
    float *Ht, *H1t, *HtP, *H1tP, *pOut;
    unsigned *tH, *tH1, *tHP, *tH1P;
    cudaGetSymbolAddress((void**)&qkv, g_qkv);
    cudaGetSymbolAddress((void**)&GI,  g_GI);
    cudaGetSymbolAddress((void**)&S,   g_S);
    cudaGetSymbolAddress((void**)&ctx, g_ctx);
    cudaGetSymbolAddress((void**)&A,   g_A);
    cudaGetSymbolAddress((void**)&AG,  g_AG);
    cudaGetSymbolAddress((void**)&Ht,  g_Ht);
    cudaGetSymbolAddress((void**)&H1t, g_H1t);
    cudaGetSymbolAddress((void**)&HtP, g_HtP);
    cudaGetSymbolAddress((void**)&H1tP,g_H1tP);
    cudaGetSymbolAddress((void**)&pOut,g_probeOut);
    cudaGetSymbolAddress((void**)&tH,  g_tagH);
    cudaGetSymbolAddress((void**)&tH1, g_tagH1);
    cudaGetSymbolAddress((void**)&tHP, g_tagHP);
    cudaGetSymbolAddress((void**)&tH1P,g_tagH1P);

    dim3 blk(256);
    // 1) qkv = x @ in_proj^T + b            [8192,3072]
    gemm_k<128,true><<<dim3(D3/128, (BB*TT)/128, 1), blk>>>(
        x, DD, 0, 0, ipw, DD, 0, 0, qkv, D3, 0, 0, DD, 1, ipb, 1.f);
    // 2) GI = x @ w_ih^T + b_ih             [8192,3072]
    gemm_k<128,true><<<dim3(D3/128, (BB*TT)/128, 1), blk>>>(
        x, DD, 0, 0, wih, DD, 0, 0, GI, D3, 0, 0, DD, 1, bih, 1.f);
    // 3) scores S[b,h] = Q K^T / 8          batched 128x [1024,1024], K=64
    gemm_k<128,true><<<dim3(TT/128, TT/128, BB*HH), blk>>>(
        qkv,      D3, (long long)TT*D3, 64,
        qkv + DD, D3, (long long)TT*D3, 64,
        S, TT, (long long)HH*TT*TT, (long long)TT*TT,
        64, HH, nullptr, 0.125f);
    // 4) DIAGNOSTIC PROBE: exact recur clone, 96 tokens, private state, dummy out.
    //    Sits in the stream slot ncu has been capturing. Time delta vs R6 = 384 sub-steps.
    recur_t<96, true><<<GBLK, PTH>>>(whh, bhh, gw, GI, GI, GI + DD,
                                     HtP, H1tP, tHP, tH1P, pOut);
    // 5) softmax rows
    softmax_k<<<BB*HH*TT, 256>>>(S);
    // 6) ctx[b,h] = S @ V                   batched 128x [1024,64], K=1024
    gemm_k<64,false><<<dim3(1, TT/128, BB*HH), blk>>>(
        S, TT, (long long)HH*TT*TT, (long long)TT*TT,
        qkv + 2*DD, D3, (long long)TT*D3, 64,
        ctx, DD, (long long)TT*DD, 64,
        TT, HH, nullptr, 1.f);
    // 7) A = ctx @ out_proj^T + b           [8192,1024]
    gemm_k<128,true><<<dim3(DD/128, (BB*TT)/128, 1), blk>>>(
        ctx, DD, 0, 0, opw, DD, 0, 0, A, DD, 0, 0, DD, 1, opb, 1.f);
    // 8) AG = A @ gate_w[:,D:]^T + gate_b   [8192,1024]
    gemm_k<128,true><<<dim3(DD/128, (BB*TT)/128, 1), blk>>>(
        A, DD, 0, 0, gw + DD, 2*DD, 0, 0, AG, DD, 0, 0, DD, 1, gb, 1.f);
    // 9) reset real h buffers + tags
    reset_k<<<32, 256>>>();
    // 10) real persistent sequential recurrence
    recur_t<TT, false><<<GBLK, PTH>>>(whh, bhh, gw, GI, A, AG,
                                      Ht, H1t, tH, tH1, out);
}

// round 8
// speedup vs baseline: 1.1660x; 1.1660x over previous
#include <cuda_runtime.h>
#include <math.h>

#define BB 8
#define TT 1024
#define DD 1024
#define HH 16
#define D3 3072

// ---------------- scratch (static device arrays; no runtime allocation) ----------------
__device__ float g_qkv[25165824];   // [B,T,3D]
__device__ float g_GI [25165824];   // [B,T,3D]  x@w_ih^T + b_ih
__device__ float g_S  [134217728];  // [B,H,T,T] attention scores
__device__ float g_ctx[8388608];    // [B,T,D]
__device__ float g_A  [8388608];    // [B,T,D]   attention output
__device__ float g_AG [8388608];    // [B,T,D]   a-part of gate preact (incl. gate_b)
__device__ float g_Ht [8192];       // transposed hidden state [d][b]
__device__ float g_H1t[8192];       // transposed post-GRU state [d][b]
__device__ unsigned g_tagH [1024];  // per-dim version tags for h
__device__ unsigned g_tagH1[1024];  // per-dim version tags for h1

// ---------------- packed f32x2 helpers ----------------
__device__ __forceinline__ void fma2(unsigned long long& d, unsigned long long a,
                                     unsigned long long b, unsigned long long c)
{
    asm("fma.rn.f32x2 %0, %1, %2, %3;" : "=l"(d) : "l"(a), "l"(b), "l"(c));
}
__device__ __forceinline__ unsigned long long add2(unsigned long long a, unsigned long long b)
{
    unsigned long long d;
    asm("add.rn.f32x2 %0, %1, %2;" : "=l"(d) : "l"(a), "l"(b));
    return d;
}
__device__ __forceinline__ unsigned long long pack2(float x)
{
    unsigned long long d; unsigned u = __float_as_uint(x);
    asm("mov.b64 %0, {%1, %2};" : "=l"(d) : "r"(u), "r"(u));
    return d;
}
__device__ __forceinline__ void unpack2(unsigned long long v, float& lo, float& hi)
{
    unsigned a, b;
    asm("mov.b64 {%0, %1}, %2;" : "=r"(a), "=r"(b) : "l"(v));
    lo = __uint_as_float(a); hi = __uint_as_float(b);
}
__device__ __forceinline__ float fsig(float x)
{
    return __fdividef(1.f, 1.f + __expf(-x));
}
__device__ __forceinline__ float ftanh(float x)
{
    return 1.f - __fdividef(2.f, __expf(2.f * x) + 1.f);
}

// ---------------- 128x128 tiled SGEMM (f32x2 core): C = scale*(A@op(B)) + bias ----------------
#define GEMM_LOAD(buf, kofs) do {                                               \
    float4 va = *(const float4*)&A[(long long)ar*lda + (kofs) + aq];            \
    As[buf][aq+0][ar]=va.x; As[buf][aq+1][ar]=va.y;                             \
    As[buf][aq+2][ar]=va.z; As[buf][aq+3][ar]=va.w;                             \
    if constexpr (TB) {                                                         \
      if (TN == 128 || t < 128) {                                               \
        float4 vb = *(const float4*)&Bp[(n0 + ar)*ldb + (kofs) + aq];           \
        Bs[buf][aq+0][ar]=vb.x; Bs[buf][aq+1][ar]=vb.y;                         \
        Bs[buf][aq+2][ar]=vb.z; Bs[buf][aq+3][ar]=vb.w;                         \
      }                                                                         \
    } else {                                                                    \
      if constexpr (TN == 128) {                                                \
        int kk = t >> 5, nn = (t & 31) * 4;                                     \
        *(float4*)&Bs[buf][kk][nn] =                                            \
            *(const float4*)&Bp[(long long)((kofs)+kk)*ldb + n0 + nn];          \
      } else {                                                                  \
        if (t < 128) { int kk = t >> 4, nn = (t & 15) * 4;                      \
          *(float4*)&Bs[buf][kk][nn] =                                          \
              *(const float4*)&Bp[(long long)((kofs)+kk)*ldb + n0 + nn]; }      \
      }                                                                         \
    }                                                                           \
  } while (0)

template<int TN, bool TB>
__global__ __launch_bounds__(256) void gemm_k(
    const float* __restrict__ A0, int lda, long long sA1, long long sA2,
    const float* __restrict__ B0, int ldb, long long sB1, long long sB2,
    float* __restrict__ C0, int ldc, long long sC1, long long sC2,
    int K, int Z2, const float* __restrict__ bias, float scale)
{
    constexpr int NJ = TN / 16;     // 8 or 4
    constexpr int NP = NJ / 2;      // accumulator pairs: 4 or 2
    int z  = blockIdx.z;
    int z1 = z / Z2, z2 = z - z1 * Z2;
    const float* A  = A0 + z1 * sA1 + z2 * sA2 + (long long)blockIdx.y * 128 * lda;
    const float* Bp = B0 + z1 * sB1 + z2 * sB2;
    float*       C  = C0 + z1 * sC1 + z2 * sC2 + (long long)blockIdx.y * 128 * ldc
                         + (long long)blockIdx.x * TN;
    long long n0 = (long long)blockIdx.x * TN;

    __shared__ float As[2][8][128];
    __shared__ float Bs[2][8][TN];
    int t = threadIdx.x, tx = t & 15, ty = t >> 4;
    int ar = t >> 1, aq = (t & 1) * 4;

    unsigned long long acc2[8][NP];
    #pragma unroll
    for (int i = 0; i < 8; i++)
        #pragma unroll
        for (int j = 0; j < NP; j++) acc2[i][j] = 0ull;

    int nk = K >> 3;
    GEMM_LOAD(0, 0);
    __syncthreads();

    for (int kt = 0; kt < nk; kt++) {
        int cb = kt & 1, nb = cb ^ 1;
        if (kt + 1 < nk) { GEMM_LOAD(nb, (kt + 1) << 3); }
        #pragma unroll
        for (int kk = 0; kk < 8; kk++) {
            float4 a0 = *(const float4*)&As[cb][kk][ty * 4];
            float4 a1 = *(const float4*)&As[cb][kk][ty * 4 + 64];
            ulonglong2 b01 = *(const ulonglong2*)&Bs[cb][kk][tx * 4];
            float av[8] = {a0.x,a0.y,a0.z,a0.w,a1.x,a1.y,a1.z,a1.w};
            if constexpr (NP == 4) {
                ulonglong2 b23 = *(const ulonglong2*)&Bs[cb][kk][tx * 4 + 64];
                #pragma unroll
                for (int i = 0; i < 8; i++) {
                    unsigned long long pa = pack2(av[i]);
                    fma2(acc2[i][0], b01.x, pa, acc2[i][0]);
                    fma2(acc2[i][1], b01.y, pa, acc2[i][1]);
                    fma2(acc2[i][2], b23.x, pa, acc2[i][2]);
                    fma2(acc2[i][3], b23.y, pa, acc2[i][3]);
                }
            } else {
                #pragma unroll
                for (int i = 0; i < 8; i++) {
                    unsigned long long pa = pack2(av[i]);
                    fma2(acc2[i][0], b01.x, pa, acc2[i][0]);
                    fma2(acc2[i][1], b01.y, pa, acc2[i][1]);
                }
            }
        }
        __syncthreads();
    }

    #pragma unroll
    for (int i = 0; i < 8; i++) {
        int row = (i < 4) ? (ty * 4 + i) : (64 + ty * 4 + (i - 4));
        #pragma unroll
        for (int jh = 0; jh < NP / 2; jh++) {
            int col = tx * 4 + jh * 64;
            float4 v;
            unpack2(acc2[i][jh*2+0], v.x, v.y);
            unpack2(acc2[i][jh*2+1], v.z, v.w);
            v.x *= scale; v.y *= scale; v.z *= scale; v.w *= scale;
            if (bias) {
                v.x += bias[n0+col]; v.y += bias[n0+col+1];
                v.z += bias[n0+col+2]; v.w += bias[n0+col+3];
            }
            *(float4*)&C[(long long)row * ldc + col] = v;
        }
    }
}

// ---------------- row softmax over 1024 columns ----------------
__global__ __launch_bounds__(256) void softmax_k(float* __restrict__ S)
{
    long long row = blockIdx.x;
    float* p = S + row * (long long)TT;
    int t = threadIdx.x;
    float v0 = p[t], v1 = p[t + 256], v2 = p[t + 512], v3 = p[t + 768];
    float m = fmaxf(fmaxf(v0, v1), fmaxf(v2, v3));
    __shared__ float sredm[8];
    __shared__ float sreds[8];
    #pragma unroll
    for (int o = 16; o; o >>= 1) m = fmaxf(m, __shfl_xor_sync(0xffffffffu, m, o));
    if ((t & 31) == 0) sredm[t >> 5] = m;
    __syncthreads();
    m = fmaxf(fmaxf(fmaxf(sredm[0], sredm[1]), fmaxf(sredm[2], sredm[3])),
              fmaxf(fmaxf(sredm[4], sredm[5]), fmaxf(sredm[6], sredm[7])));
    v0 = expf(v0 - m); v1 = expf(v1 - m); v2 = expf(v2 - m); v3 = expf(v3 - m);
    float s = (v0 + v1) + (v2 + v3);
    #pragma unroll
    for (int o = 16; o; o >>= 1) s += __shfl_xor_sync(0xffffffffu, s, o);
    if ((t & 31) == 0) sreds[t >> 5] = s;
    __syncthreads();
    s = ((sreds[0] + sreds[1]) + (sreds[2] + sreds[3]))
      + ((sreds[4] + sreds[5]) + (sreds[6] + sreds[7]));
    float inv = 1.f / s;
    p[t] = v0 * inv; p[t + 256] = v1 * inv; p[t + 512] = v2 * inv; p[t + 768] = v3 * inv;
}

// ---------------- state / tag reset ----------------
__global__ void reset_k()
{
    int i = blockIdx.x * blockDim.x + threadIdx.x;
    if (i < BB * DD) { g_Ht[i] = 0.f; g_H1t[i] = 0.f; }
    if (i < DD) { g_tagH[i] = 0u; g_tagH1[i] = 0u; }
}

// ---------------- persistent recurrent kernel (per-dim tagged dataflow) ----------------
#define GBLK 128
#define PTH  512

// Warp-coalesced wait with backoff: all 64 tags for this warp's k-range reach tgt.
__device__ __forceinline__ void wait_tags(const unsigned* tags, int w, unsigned tgt)
{
    int lane = threadIdx.x & 31;
    const unsigned* p0 = tags + w * 64 + lane;
    const unsigned* p1 = p0 + 32;
    unsigned v0, v1;
    int miss = 0;
    while (true) {
        asm volatile("ld.acquire.gpu.u32 %0, [%1];" : "=r"(v0) : "l"(p0) : "memory");
        asm volatile("ld.acquire.gpu.u32 %0, [%1];" : "=r"(v1) : "l"(p1) : "memory");
        if (__all_sync(0xffffffffu, (v0 >= tgt) & (v1 >= tgt))) break;
        if (++miss > 3) __nanosleep(30);
    }
}

__global__ __launch_bounds__(PTH, 1) void recur_k(
    const float* __restrict__ w_hh, const float* __restrict__ b_hh,
    const float* __restrict__ gate_w, float* __restrict__ out)
{
    __shared__ unsigned long long part[16 * 96];   // per-warp partials
    __shared__ unsigned long long ghs[96];         // phase1 reduced (u64 pairs)
    __shared__ unsigned long long g2s[32];         // phase2 reduced
    __shared__ float bs1[24];

    int t = threadIdx.x, g = blockIdx.x;
    int d0 = g * 8;
    int w = t >> 5, lane = t & 31;

    int rsub = lane >> 2, kq1 = lane & 3;   // phase1 matvec roles
    int rg2 = lane >> 3, kq2 = lane & 7;    // phase2 matvec roles
    // elementwise roles on the TOP warps (highest arbiter priority)
    int te = t - 448;                       // valid for t >= 448
    int ed = te >> 3, eb = te & 7;
    int dg = d0 + (ed & 7);
    unsigned pubmask = 0xFFu << ((ed & 3) * 8);

    // ---- weights resident in registers ----
    float w1[3][16];
    #pragma unroll
    for (int q = 0; q < 3; q++) {
        int rho = rsub * 3 + q;
        const float* wr = w_hh + (size_t)((rho >> 3) * DD + d0 + (rho & 7)) * DD
                        + w * 64 + kq1;
        #pragma unroll
        for (int i = 0; i < 16; i++) w1[q][i] = wr[4 * i];
    }
    float w2[2][8];
    #pragma unroll
    for (int r = 0; r < 2; r++) {
        const float* wr = gate_w + (size_t)(d0 + rg2 * 2 + r) * (2 * DD)
                        + w * 64 + kq2;
        #pragma unroll
        for (int i = 0; i < 8; i++) w2[r][i] = wr[8 * i];
    }
    if (t < 24) bs1[t] = b_hh[(t >> 3) * DD + d0 + (t & 7)];
    __syncthreads();

    unsigned e = 0;
    float h_own = 0.f, h1_own = 0.f;

    const ulonglong2* Hg  = (const ulonglong2*)g_Ht;
    const ulonglong2* H1g = (const ulonglong2*)g_H1t;

    // per-token operands, prefetched one token ahead (DRAM-latency loads)
    float girC = 0, gizC = 0, ginC = 0, avC = 0, agvC = 0;
    float girN = 0, gizN = 0, ginN = 0, avN = 0, agvN = 0;
    if (t >= 448) {
        size_t gb = ((size_t)(eb * TT)) * D3 + dg;
        girC = __ldg(&g_GI[gb]); gizC = __ldg(&g_GI[gb + DD]); ginC = __ldg(&g_GI[gb + 2 * DD]);
        size_t ab = ((size_t)(eb * TT)) * DD + dg;
        avC = __ldg(&g_A[ab]); agvC = __ldg(&g_AG[ab]);
    }

    for (int tok = 0; tok < TT; tok++) {
        #pragma unroll 1
        for (int s = 0; s < 4; s++) {
            // ---- phase 1: gh = W_hh . h ----
            {
                wait_tags(g_tagH, w, e);
                unsigned long long acc[12];
                #pragma unroll
                for (int j = 0; j < 12; j++) acc[j] = 0ull;
                int kb = w * 64 + kq1;
                #pragma unroll
                for (int i = 0; i < 16; i++) {
                    int ii = (i + g) & 15;                 // block-staggered order
                    int k = kb + 4 * ii;
                    ulonglong2 p0 = __ldcg(&Hg[k * 2]);
                    ulonglong2 p1 = __ldcg(&Hg[k * 2 + 1]);
                    #pragma unroll
                    for (int q = 0; q < 3; q++) {
                        unsigned long long wd = pack2(w1[q][ii]);
                        fma2(acc[q*4+0], p0.x, wd, acc[q*4+0]);
                        fma2(acc[q*4+1], p0.y, wd, acc[q*4+1]);
                        fma2(acc[q*4+2], p1.x, wd, acc[q*4+2]);
                        fma2(acc[q*4+3], p1.y, wd, acc[q*4+3]);
                    }
                }
                #pragma unroll
                for (int o = 1; o <= 2; o <<= 1)
                    #pragma unroll
                    for (int j = 0; j < 12; j++)
                        acc[j] = add2(acc[j], __shfl_xor_sync(0xffffffffu, acc[j], o));
                if (kq1 == 0) {
                    #pragma unroll
                    for (int j = 0; j < 12; j++) part[w * 96 + rsub * 12 + j] = acc[j];
                }
            }
            __syncthreads();
            if (t >= 416) {                                // warps 13-15 reduce
                int tr = t - 416;
                unsigned long long d = part[tr];
                #pragma unroll
                for (int wv = 1; wv < 16; wv++) d = add2(d, part[wv * 96 + tr]);
                ghs[tr] = d;
            }
            __syncthreads();

            // ---- GRU elementwise -> publish h1 (top warps) ----
            if (t >= 448) {
                const float* ghf = (const float*)ghs;
                float gh[3];
                #pragma unroll
                for (int c = 0; c < 3; c++) {
                    int rho = c * 8 + ed;
                    int o = (rho / 3) * 12 + (rho % 3) * 4 + (eb >> 1);
                    gh[c] = ghf[o * 2 + (eb & 1)] + bs1[rho];
                }
                float rr = fsig(girC + gh[0]);
                float zz = fsig(gizC + gh[1]);
                float nn = ftanh(ginC + rr * gh[2]);
                h1_own = (1.f - zz) * nn + zz * h_own;
                __stcg(&g_H1t[dg * 8 + eb], h1_own);
                __syncwarp(pubmask);
                if (eb == 0) {
                    unsigned tg = e + 1;
                    asm volatile("st.release.gpu.u32 [%0], %1;"
                                 :: "l"(&g_tagH1[dg]), "r"(tg) : "memory");
                }
                // prefetch next token's operands into the idle wait window
                if (s == 0 && tok + 1 < TT) {
                    size_t gb = ((size_t)(eb * TT + tok + 1)) * D3 + dg;
                    girN = __ldg(&g_GI[gb]); gizN = __ldg(&g_GI[gb + DD]);
                    ginN = __ldg(&g_GI[gb + 2 * DD]);
                    size_t ab = ((size_t)(eb * TT + tok + 1)) * DD + dg;
                    avN = __ldg(&g_A[ab]); agvN = __ldg(&g_AG[ab]);
                }
            }

            // ---- phase 2: gate dot ----
            {
                wait_tags(g_tagH1, w, e + 1);
                unsigned long long a2[8];
                #pragma unroll
                for (int j = 0; j < 8; j++) a2[j] = 0ull;
                int kb = w * 64 + kq2;
                #pragma unroll
                for (int i = 0; i < 8; i++) {
                    int ii = (i + g) & 7;                  // block-staggered order
                    int k = kb + 8 * ii;
                    ulonglong2 p0 = __ldcg(&H1g[k * 2]);
                    ulonglong2 p1 = __ldcg(&H1g[k * 2 + 1]);
                    #pragma unroll
                    for (int r = 0; r < 2; r++) {
                        unsigned long long wd = pack2(w2[r][ii]);
                        fma2(a2[r*4+0], p0.x, wd, a2[r*4+0]);
                        fma2(a2[r*4+1], p0.y, wd, a2[r*4+1]);
                        fma2(a2[r*4+2], p1.x, wd, a2[r*4+2]);
                        fma2(a2[r*4+3], p1.y, wd, a2[r*4+3]);
                    }
                }
                #pragma unroll
                for (int o = 1; o <= 4; o <<= 1)
                    #pragma unroll
                    for (int j = 0; j < 8; j++)
                        a2[j] = add2(a2[j], __shfl_xor_sync(0xffffffffu, a2[j], o));
                if (kq2 == 0) {
                    #pragma unroll
                    for (int j = 0; j < 8; j++) part[w * 32 + rg2 * 8 + j] = a2[j];
                }
            }
            __syncthreads();
            if (t >= 480) {                                // warp 15 reduces
                int tr = t - 480;
                unsigned long long d = part[tr];
                #pragma unroll
                for (int wv = 1; wv < 16; wv++) d = add2(d, part[wv * 32 + tr]);
                g2s[tr] = d;
            }
            __syncthreads();

            // ---- gate elementwise -> publish new h (+ output on last sub-step) ----
            if (t >= 448) {
                const float* g2f = (const float*)g2s;
                float dot = g2f[ed * 8 + eb];
                float gv  = fsig(dot + agvC);
                h_own = gv * h1_own + (1.f - gv) * avC;
                __stcg(&g_Ht[dg * 8 + eb], h_own);
                if (s == 3) out[((size_t)(eb * TT + tok)) * DD + dg] = h_own;
                __syncwarp(pubmask);
                if (eb == 0) {
                    unsigned tg = e + 1;
                    asm volatile("st.release.gpu.u32 [%0], %1;"
                                 :: "l"(&g_tagH[dg]), "r"(tg) : "memory");
                }
            }
            e++;
        }
        girC = girN; gizC = gizN; ginC = ginN; avC = avN; agvC = agvN;
    }
}

// ---------------- launch ----------------
extern "C" void kernel_launch(void* const* d_in, const int* in_sizes, int n_in,
                              void* d_out, int out_size)
{
    (void)in_sizes; (void)n_in; (void)out_size;
    const float* x   = (const float*)d_in[0];
    const float* ipw = (const float*)d_in[1];
    const float* ipb = (const float*)d_in[2];
    const float* opw = (const float*)d_in[3];
    const float* opb = (const float*)d_in[4];
    const float* wih = (const float*)d_in[5];
    const float* whh = (const float*)d_in[6];
    const float* bih = (const float*)d_in[7];
    const float* bhh = (const float*)d_in[8];
    const float* gw  = (const float*)d_in[9];
    const float* gb  = (const float*)d_in[10];
    float* out = (float*)d_out;

    float *qkv, *GI, *S, *ctx, *A, *AG;
    cudaGetSymbolAddress((void**)&qkv, g_qkv);
    cudaGetSymbolAddress((void**)&GI,  g_GI);
    cudaGetSymbolAddress((void**)&S,   g_S);
    cudaGetSymbolAddress((void**)&ctx, g_ctx);
    cudaGetSymbolAddress((void**)&A,   g_A);
    cudaGetSymbolAddress((void**)&AG,  g_AG);

    dim3 blk(256);
    // 1) qkv = x @ in_proj^T + b            [8192,3072]
    gemm_k<128,true><<<dim3(D3/128, (BB*TT)/128, 1), blk>>>(
        x, DD, 0, 0, ipw, DD, 0, 0, qkv, D3, 0, 0, DD, 1, ipb, 1.f);
    // 2) GI = x @ w_ih^T + b_ih             [8192,3072]
    gemm_k<128,true><<<dim3(D3/128, (BB*TT)/128, 1), blk>>>(
        x, DD, 0, 0, wih, DD, 0, 0, GI, D3, 0, 0, DD, 1, bih, 1.f);
    // 3) scores S[b,h] = Q K^T / 8          batched 128x [1024,1024], K=64
    gemm_k<128,true><<<dim3(TT/128, TT/128, BB*HH), blk>>>(
        qkv,      D3, (long long)TT*D3, 64,
        qkv + DD, D3, (long long)TT*D3, 64,
        S, TT, (long long)HH*TT*TT, (long long)TT*TT,
        64, HH, nullptr, 0.125f);
    // 4) softmax rows
    softmax_k<<<BB*HH*TT, 256>>>(S);
    // 5) ctx[b,h] = S @ V                   batched 128x [1024,64], K=1024
    gemm_k<64,false><<<dim3(1, TT/128, BB*HH), blk>>>(
        S, TT, (long long)HH*TT*TT, (long long)TT*TT,
        qkv + 2*DD, D3, (long long)TT*D3, 64,
        ctx, DD, (long long)TT*DD, 64,
        TT, HH, nullptr, 1.f);
    // 6) A = ctx @ out_proj^T + b           [8192,1024]
    gemm_k<128,true><<<dim3(DD/128, (BB*TT)/128, 1), blk>>>(
        ctx, DD, 0, 0, opw, DD, 0, 0, A, DD, 0, 0, DD, 1, opb, 1.f);
    // 7) AG = A @ gate_w[:,D:]^T + gate_b   [8192,1024]
    gemm_k<128,true><<<dim3(DD/128, (BB*TT)/128, 1), blk>>>(
        A, DD, 0, 0, gw + DD, 2*DD, 0, 0, AG, DD, 0, 0, DD, 1, gb, 1.f);
    // 8) reset h buffers + tags (deterministic across graph replays)
    reset_k<<<32, 256>>>();
    // 9) persistent sequential recurrence (tagged dataflow, inverted warp roles)
    recur_k<<<GBLK, PTH>>>(whh, bhh, gw, out);
}